// round 1
// baseline (speedup 1.0000x reference)
#include <cuda_runtime.h>
#include <cuda_bf16.h>
#include <math.h>

#define BB 2
#define NRES 384
#define CS 256
#define CZ 128
#define NODE_IN 145
#define HP 132           // Hs pitch (floats), 132*4=528 bytes (16B aligned rows)
#define PI_F 3.14159265358979323846f

// ---------------- scratch (no allocation allowed) ----------------
__device__ float g_NIN[BB * NRES * NODE_IN];   // node_in
__device__ float g_NA [BB * NRES * CZ];        // prot_i @ ew1[0:73]
__device__ float g_NB [BB * NRES * CZ];        // prot_j @ ew1[73:146]
__device__ float g_REL[767 * CZ];              // idx_emb(rel) @ ew1[146:178]

// ---------------- kernel 1: per-node features + A/B projections ----------------
__global__ __launch_bounds__(128) void prep_node_kernel(
    const float* __restrict__ atom10, const int* __restrict__ seq_idx,
    const float* __restrict__ t, const float* __restrict__ fixed_mask,
    const float* __restrict__ sc_trans, const float* __restrict__ sc_rots,
    const float* __restrict__ sc_atom14, const float* __restrict__ ew1)
{
    __shared__ float pt[73];
    __shared__ float nin[NODE_IN];
    const int row = blockIdx.x;           // b*NRES + i
    const int b = row / NRES;
    const int tid = threadIdx.x;

    if (tid < 16) {
        // timestep embedding (dim 32)
        float fr = expf((float)tid * (-logf(10000.0f) / 15.0f));
        float ang = t[b] * 10000.0f * fr;
        pt[tid]      = sinf(ang);
        pt[16 + tid] = cosf(ang);
        // index embedding of seq_idx (dim 32)
        float den = powf(2056.0f, (float)tid / 16.0f);
        float ang2 = (float)seq_idx[row] * PI_F / den;
        nin[73 + tid]      = sinf(ang2);
        nin[73 + 16 + tid] = cosf(ang2);
    }
    if (tid == 0) pt[32] = fixed_mask[row];
    if (tid < 30) pt[33 + tid] = atom10[row * 30 + tid];
    if (tid < 10) {
        const float* ap = atom10 + row * 30 + tid * 3;
        float x = ap[0], y = ap[1], z = ap[2];
        float d = sqrtf(x * x + y * y + z * z);
        pt[63 + tid] = 1.0f / (1.0f + d * d);
        // local frame atoms
        const float* tr = sc_trans + row * 3;
        const float* R  = sc_rots  + row * 9;     // [j][i2] row-major
        const float* at = sc_atom14 + row * 42 + (4 + tid) * 3;
        float d0 = at[0] - tr[0], d1 = at[1] - tr[1], d2 = at[2] - tr[2];
        float l0 = d0 * R[0] + d1 * R[3] + d2 * R[6];
        float l1 = d0 * R[1] + d1 * R[4] + d2 * R[7];
        float l2 = d0 * R[2] + d1 * R[5] + d2 * R[8];
        nin[105 + tid * 3 + 0] = l0;
        nin[105 + tid * 3 + 1] = l1;
        nin[105 + tid * 3 + 2] = l2;
        float ld = sqrtf(l0 * l0 + l1 * l1 + l2 * l2);
        nin[135 + tid] = 1.0f / (1.0f + ld);
    }
    __syncthreads();
    if (tid < 73) nin[tid] = pt[tid];
    __syncthreads();

    for (int x = tid; x < NODE_IN; x += 128)
        g_NIN[row * NODE_IN + x] = nin[x];

    if (tid < CZ) {
        float accA = 0.f, accB = 0.f;
        #pragma unroll 1
        for (int f = 0; f < 73; f++) {
            float p = pt[f];
            accA = fmaf(p, ew1[f * CZ + tid], accA);
            accB = fmaf(p, ew1[(73 + f) * CZ + tid], accB);
        }
        g_NA[row * CZ + tid] = accA;
        g_NB[row * CZ + tid] = accB;
    }
}

// ---------------- kernel 2: relative-position table ----------------
__global__ __launch_bounds__(128) void prep_rel_kernel(const float* __restrict__ ew1)
{
    __shared__ float emb[32];
    const int r = blockIdx.x;             // rel = r - 383
    const int tid = threadIdx.x;
    if (tid < 16) {
        float v = (float)(r - 383);
        float den = powf(2056.0f, (float)tid / 16.0f);
        float ang = v * PI_F / den;
        emb[tid]      = sinf(ang);
        emb[16 + tid] = cosf(ang);
    }
    __syncthreads();
    float acc = 0.f;
    #pragma unroll
    for (int k = 0; k < 32; k++)
        acc = fmaf(emb[k], ew1[(146 + k) * CZ + tid], acc);
    g_REL[r * CZ + tid] = acc;
}

// ---------------- kernel 3: node MLP + LN ----------------
__global__ __launch_bounds__(256) void node_mlp_kernel(
    const float* __restrict__ nw1, const float* __restrict__ nb1,
    const float* __restrict__ nw2, const float* __restrict__ nb2,
    const float* __restrict__ nw3, const float* __restrict__ nb3,
    const float* __restrict__ ng,  const float* __restrict__ nbt,
    float* __restrict__ outN)
{
    __shared__ float nin[NODE_IN];
    __shared__ float h[CS];
    __shared__ float sred[8], s2red[8];
    const int row = blockIdx.x;
    const int tid = threadIdx.x;

    if (tid < NODE_IN) nin[tid] = g_NIN[row * NODE_IN + tid];
    __syncthreads();

    float a = nb1[tid];
    #pragma unroll 1
    for (int f = 0; f < NODE_IN; f++)
        a = fmaf(nin[f], nw1[f * CS + tid], a);
    h[tid] = fmaxf(a, 0.f);
    __syncthreads();

    float a2 = nb2[tid];
    #pragma unroll 4
    for (int k = 0; k < CS; k++)
        a2 = fmaf(h[k], nw2[k * CS + tid], a2);
    a2 = fmaxf(a2, 0.f);
    __syncthreads();
    h[tid] = a2;
    __syncthreads();

    float a3 = nb3[tid];
    #pragma unroll 4
    for (int k = 0; k < CS; k++)
        a3 = fmaf(h[k], nw3[k * CS + tid], a3);

    // LayerNorm over 256
    float s = a3, s2 = a3 * a3;
    #pragma unroll
    for (int o = 16; o > 0; o >>= 1) {
        s  += __shfl_xor_sync(0xffffffffu, s,  o);
        s2 += __shfl_xor_sync(0xffffffffu, s2, o);
    }
    if ((tid & 31) == 0) { sred[tid >> 5] = s; s2red[tid >> 5] = s2; }
    __syncthreads();
    float S = 0.f, S2 = 0.f;
    #pragma unroll
    for (int w = 0; w < 8; w++) { S += sred[w]; S2 += s2red[w]; }
    float mu = S * (1.0f / CS);
    float var = S2 * (1.0f / CS) - mu * mu;
    float rs = rsqrtf(var + 1e-5f);
    outN[row * CS + tid] = (a3 - mu) * rs * ng[tid] + nbt[tid];
}

// ---------------- kernel 4: edge MLP (dominant) ----------------
__global__ __launch_bounds__(256) void edge_kernel(
    const int* __restrict__ seq_idx, const float* __restrict__ sc_trans,
    const float* __restrict__ ew1, const float* __restrict__ eb1,
    const float* __restrict__ ew2, const float* __restrict__ eb2,
    const float* __restrict__ ew3, const float* __restrict__ eb3,
    const float* __restrict__ eg,  const float* __restrict__ ebt,
    float* __restrict__ outE)
{
    extern __shared__ float sm[];
    float* W2s  = sm;                       // 128*128
    float* W3s  = W2s + CZ * CZ;            // 128*128
    float* Hs   = W3s + CZ * CZ;            // 128*HP  (k-major: Hs[k][m])
    float* base = Hs + CZ * HP;             // 128
    int*  relS  = (int*)(base + CZ);        // 128
    int*  binS  = relS + CZ;                // 128

    const int jt = blockIdx.x, i = blockIdx.y, b = blockIdx.z;
    const int j0 = jt * 128;
    const int tid = threadIdx.x;
    const int row_i = b * NRES + i;

    // weights -> smem
    {
        const float4* w2v = (const float4*)ew2;
        const float4* w3v = (const float4*)ew3;
        float4* W2v = (float4*)W2s;
        float4* W3v = (float4*)W3s;
        for (int x = tid; x < (CZ * CZ) / 4; x += 256) { W2v[x] = w2v[x]; W3v[x] = w3v[x]; }
    }
    if (tid < CZ) base[tid] = g_NA[row_i * CZ + tid] + eb1[tid];
    if (tid < 128) {
        const int j = j0 + tid;
        const int row_j = b * NRES + j;
        int r = seq_idx[row_i] - seq_idx[row_j] + 383;
        relS[tid] = min(max(r, 0), 766);
        float dx = sc_trans[row_i * 3 + 0] - sc_trans[row_j * 3 + 0];
        float dy = sc_trans[row_i * 3 + 1] - sc_trans[row_j * 3 + 1];
        float dz = sc_trans[row_i * 3 + 2] - sc_trans[row_j * 3 + 2];
        float d = sqrtf(dx * dx + dy * dy + dz * dz);
        int bin = -1;
        const double step = (20.0 - 1e-05) / 21.0;
        #pragma unroll
        for (int k = 0; k < 22; k++) {
            float lo = (float)(1e-05 + k * step);
            float hi = (k < 21) ? (float)(1e-05 + (k + 1) * step) : 1e8f;
            if (d > lo && d < hi) bin = k;
        }
        binS[tid] = bin;
    }
    __syncthreads();

    // layer 1 via factorization: h1[m][k] = relu(base[k] + B[j][k] + REL[rel][k] + dgram_row[k])
    {
        const int k = tid & 127;
        const int mb = (tid >> 7) * 64;
        const float bk = base[k];
        const float* nbp = g_NB + ((size_t)b * NRES + j0) * CZ + k;
        #pragma unroll 4
        for (int mm = 0; mm < 64; mm++) {
            const int m = mb + mm;
            float v = bk + nbp[(size_t)m * CZ] + g_REL[relS[m] * CZ + k];
            int bi = binS[m];
            if (bi >= 0) v += ew1[(178 + bi) * CZ + k];
            Hs[k * HP + m] = fmaxf(v, 0.f);
        }
    }
    __syncthreads();

    const int tx = tid & 15, ty = tid >> 4;
    const int n0 = tx * 8, m0 = ty * 8;

    float acc[8][8];

    // ---- GEMM 1: h2 = relu(h1 @ W2 + b2) ----
    #pragma unroll
    for (int r = 0; r < 8; r++)
        #pragma unroll
        for (int c = 0; c < 8; c++) acc[r][c] = 0.f;

    #pragma unroll 4
    for (int k = 0; k < CZ; k++) {
        float4 a0 = *(const float4*)&Hs[k * HP + m0];
        float4 a1 = *(const float4*)&Hs[k * HP + m0 + 4];
        float4 b0 = *(const float4*)&W2s[k * CZ + n0];
        float4 b1 = *(const float4*)&W2s[k * CZ + n0 + 4];
        float av[8] = {a0.x, a0.y, a0.z, a0.w, a1.x, a1.y, a1.z, a1.w};
        float bv[8] = {b0.x, b0.y, b0.z, b0.w, b1.x, b1.y, b1.z, b1.w};
        #pragma unroll
        for (int r = 0; r < 8; r++)
            #pragma unroll
            for (int c = 0; c < 8; c++)
                acc[r][c] = fmaf(av[r], bv[c], acc[r][c]);
    }
    {
        #pragma unroll
        for (int c = 0; c < 8; c++) {
            float bc = eb2[n0 + c];
            #pragma unroll
            for (int r = 0; r < 8; r++)
                acc[r][c] = fmaxf(acc[r][c] + bc, 0.f);
        }
    }
    __syncthreads();
    // store h2 transposed back into Hs (k-major for GEMM2)
    #pragma unroll
    for (int c = 0; c < 8; c++) {
        float4 v0 = make_float4(acc[0][c], acc[1][c], acc[2][c], acc[3][c]);
        float4 v1 = make_float4(acc[4][c], acc[5][c], acc[6][c], acc[7][c]);
        *(float4*)&Hs[(n0 + c) * HP + m0]     = v0;
        *(float4*)&Hs[(n0 + c) * HP + m0 + 4] = v1;
    }
    __syncthreads();

    // ---- GEMM 2: h3 = h2 @ W3 + b3 ----
    #pragma unroll
    for (int r = 0; r < 8; r++)
        #pragma unroll
        for (int c = 0; c < 8; c++) acc[r][c] = 0.f;

    #pragma unroll 4
    for (int k = 0; k < CZ; k++) {
        float4 a0 = *(const float4*)&Hs[k * HP + m0];
        float4 a1 = *(const float4*)&Hs[k * HP + m0 + 4];
        float4 b0 = *(const float4*)&W3s[k * CZ + n0];
        float4 b1 = *(const float4*)&W3s[k * CZ + n0 + 4];
        float av[8] = {a0.x, a0.y, a0.z, a0.w, a1.x, a1.y, a1.z, a1.w};
        float bv[8] = {b0.x, b0.y, b0.z, b0.w, b1.x, b1.y, b1.z, b1.w};
        #pragma unroll
        for (int r = 0; r < 8; r++)
            #pragma unroll
            for (int c = 0; c < 8; c++)
                acc[r][c] = fmaf(av[r], bv[c], acc[r][c]);
    }
    #pragma unroll
    for (int c = 0; c < 8; c++) {
        float bc = eb3[n0 + c];
        #pragma unroll
        for (int r = 0; r < 8; r++)
            acc[r][c] += bc;
    }

    // ---- LayerNorm over n (128) per row m, reduce across 16 tx lanes ----
    float egv[8], ebv[8];
    #pragma unroll
    for (int c = 0; c < 8; c++) { egv[c] = eg[n0 + c]; ebv[c] = ebt[n0 + c]; }

    #pragma unroll
    for (int r = 0; r < 8; r++) {
        float s = 0.f, s2 = 0.f;
        #pragma unroll
        for (int c = 0; c < 8; c++) { float v = acc[r][c]; s += v; s2 += v * v; }
        #pragma unroll
        for (int o = 8; o > 0; o >>= 1) {
            s  += __shfl_xor_sync(0xffffffffu, s,  o);
            s2 += __shfl_xor_sync(0xffffffffu, s2, o);
        }
        float mu = s * (1.0f / CZ);
        float var = s2 * (1.0f / CZ) - mu * mu;
        float rs = rsqrtf(var + 1e-5f);
        const int m = j0 + m0 + r;
        float* op = outE + ((((size_t)b * NRES + i) * NRES) + m) * CZ + n0;
        float o0[4], o1[4];
        #pragma unroll
        for (int c = 0; c < 4; c++) o0[c] = (acc[r][c] - mu) * rs * egv[c] + ebv[c];
        #pragma unroll
        for (int c = 0; c < 4; c++) o1[c] = (acc[r][4 + c] - mu) * rs * egv[4 + c] + ebv[4 + c];
        *(float4*)op       = make_float4(o0[0], o0[1], o0[2], o0[3]);
        *(float4*)(op + 4) = make_float4(o1[0], o1[1], o1[2], o1[3]);
    }
}

// ---------------- launch ----------------
extern "C" void kernel_launch(void* const* d_in, const int* in_sizes, int n_in,
                              void* d_out, int out_size)
{
    const float* atom10     = (const float*)d_in[0];
    const int*   seq_idx    = (const int*)  d_in[1];
    const float* t          = (const float*)d_in[2];
    const float* fixed_mask = (const float*)d_in[3];
    /* d_in[4] node_mask unused */
    const float* sc_trans   = (const float*)d_in[5];
    const float* sc_rots    = (const float*)d_in[6];
    const float* sc_atom14  = (const float*)d_in[7];
    const float* nw1 = (const float*)d_in[8];
    const float* nb1 = (const float*)d_in[9];
    const float* nw2 = (const float*)d_in[10];
    const float* nb2 = (const float*)d_in[11];
    const float* nw3 = (const float*)d_in[12];
    const float* nb3 = (const float*)d_in[13];
    const float* ng  = (const float*)d_in[14];
    const float* nbt = (const float*)d_in[15];
    const float* ew1 = (const float*)d_in[16];
    const float* eb1 = (const float*)d_in[17];
    const float* ew2 = (const float*)d_in[18];
    const float* eb2 = (const float*)d_in[19];
    const float* ew3 = (const float*)d_in[20];
    const float* eb3 = (const float*)d_in[21];
    const float* eg  = (const float*)d_in[22];
    const float* ebt = (const float*)d_in[23];

    float* outN = (float*)d_out;
    float* outE = outN + (size_t)BB * NRES * CS;   // node first, then edge

    const int smem_edge = (CZ * CZ * 2 + CZ * HP + CZ) * 4 + 2 * CZ * 4;
    cudaFuncSetAttribute(edge_kernel, cudaFuncAttributeMaxDynamicSharedMemorySize, smem_edge);

    prep_node_kernel<<<BB * NRES, 128>>>(atom10, seq_idx, t, fixed_mask,
                                         sc_trans, sc_rots, sc_atom14, ew1);
    prep_rel_kernel<<<767, 128>>>(ew1);
    node_mlp_kernel<<<BB * NRES, 256>>>(nw1, nb1, nw2, nb2, nw3, nb3, ng, nbt, outN);
    edge_kernel<<<dim3(NRES / 128, NRES, BB), 256, smem_edge>>>(
        seq_idx, sc_trans, ew1, eb1, ew2, eb2, ew3, eb3, eg, ebt, outE);
}

// round 3
// speedup vs baseline: 1.3474x; 1.3474x over previous
#include <cuda_runtime.h>
#include <cuda_bf16.h>
#include <math.h>

#define BB 2
#define NRES 384
#define CS 256
#define CZ 128
#define NODE_IN 145
#define HP 132           // Hs pitch (floats), 132*4=528 bytes (16B aligned rows)
#define NROWS 8          // rows per CTA in node_mlp
#define PI_F 3.14159265358979323846f

typedef unsigned long long u64;

// ---------------- packed f32x2 helpers (Blackwell FFMA2) ----------------
__device__ __forceinline__ void ffma2(u64 &d, u64 a, u64 b) {
    asm("fma.rn.f32x2 %0, %1, %2, %0;" : "+l"(d) : "l"(a), "l"(b));
}
__device__ __forceinline__ u64 pack2(float x) {
    u64 r; asm("mov.b64 %0, {%1, %1};" : "=l"(r) : "f"(x)); return r;
}
__device__ __forceinline__ float2 unpack2(u64 v) {
    float2 f; asm("mov.b64 {%0, %1}, %2;" : "=f"(f.x), "=f"(f.y) : "l"(v)); return f;
}

// ---------------- scratch (no allocation allowed) ----------------
__device__ float g_NIN[BB * NRES * NODE_IN];   // node_in
__device__ float g_NA [BB * NRES * CZ];        // prot_i @ ew1[0:73]
__device__ float g_NB [BB * NRES * CZ];        // prot_j @ ew1[73:146]
__device__ float g_REL[767 * CZ];              // idx_emb(rel) @ ew1[146:178]

// ---------------- kernel 1: per-node features + A/B projections ----------------
__global__ __launch_bounds__(128) void prep_node_kernel(
    const float* __restrict__ atom10, const int* __restrict__ seq_idx,
    const float* __restrict__ t, const float* __restrict__ fixed_mask,
    const float* __restrict__ sc_trans, const float* __restrict__ sc_rots,
    const float* __restrict__ sc_atom14, const float* __restrict__ ew1)
{
    __shared__ float pt[73];
    __shared__ float nin[NODE_IN];
    const int row = blockIdx.x;           // b*NRES + i
    const int b = row / NRES;
    const int tid = threadIdx.x;

    if (tid < 16) {
        // timestep embedding (dim 32)
        float fr = expf((float)tid * (-logf(10000.0f) / 15.0f));
        float ang = t[b] * 10000.0f * fr;
        pt[tid]      = sinf(ang);
        pt[16 + tid] = cosf(ang);
        // index embedding of seq_idx (dim 32)
        float den = powf(2056.0f, (float)tid / 16.0f);
        float ang2 = (float)seq_idx[row] * PI_F / den;
        nin[73 + tid]      = sinf(ang2);
        nin[73 + 16 + tid] = cosf(ang2);
    }
    if (tid == 0) pt[32] = fixed_mask[row];
    if (tid < 30) pt[33 + tid] = atom10[row * 30 + tid];
    if (tid < 10) {
        const float* ap = atom10 + row * 30 + tid * 3;
        float x = ap[0], y = ap[1], z = ap[2];
        float d = sqrtf(x * x + y * y + z * z);
        pt[63 + tid] = 1.0f / (1.0f + d * d);
        // local frame atoms
        const float* tr = sc_trans + row * 3;
        const float* R  = sc_rots  + row * 9;     // [j][i2] row-major
        const float* at = sc_atom14 + row * 42 + (4 + tid) * 3;
        float d0 = at[0] - tr[0], d1 = at[1] - tr[1], d2 = at[2] - tr[2];
        float l0 = d0 * R[0] + d1 * R[3] + d2 * R[6];
        float l1 = d0 * R[1] + d1 * R[4] + d2 * R[7];
        float l2 = d0 * R[2] + d1 * R[5] + d2 * R[8];
        nin[105 + tid * 3 + 0] = l0;
        nin[105 + tid * 3 + 1] = l1;
        nin[105 + tid * 3 + 2] = l2;
        float ld = sqrtf(l0 * l0 + l1 * l1 + l2 * l2);
        nin[135 + tid] = 1.0f / (1.0f + ld);
    }
    __syncthreads();
    if (tid < 73) nin[tid] = pt[tid];
    __syncthreads();

    for (int x = tid; x < NODE_IN; x += 128)
        g_NIN[row * NODE_IN + x] = nin[x];

    if (tid < CZ) {
        float accA = 0.f, accB = 0.f;
        #pragma unroll 4
        for (int f = 0; f < 73; f++) {
            float p = pt[f];
            accA = fmaf(p, ew1[f * CZ + tid], accA);
            accB = fmaf(p, ew1[(73 + f) * CZ + tid], accB);
        }
        g_NA[row * CZ + tid] = accA;
        g_NB[row * CZ + tid] = accB;
    }
}

// ---------------- kernel 2: relative-position table ----------------
__global__ __launch_bounds__(128) void prep_rel_kernel(const float* __restrict__ ew1)
{
    __shared__ float emb[32];
    const int r = blockIdx.x;             // rel = r - 383
    const int tid = threadIdx.x;
    if (tid < 16) {
        float v = (float)(r - 383);
        float den = powf(2056.0f, (float)tid / 16.0f);
        float ang = v * PI_F / den;
        emb[tid]      = sinf(ang);
        emb[16 + tid] = cosf(ang);
    }
    __syncthreads();
    float acc = 0.f;
    #pragma unroll
    for (int k = 0; k < 32; k++)
        acc = fmaf(emb[k], ew1[(146 + k) * CZ + tid], acc);
    g_REL[r * CZ + tid] = acc;
}

// ---------------- kernel 3: node MLP + LN (8 rows/CTA, weight reads amortized) ----------------
__global__ __launch_bounds__(256) void node_mlp_kernel(
    const float* __restrict__ nw1, const float* __restrict__ nb1,
    const float* __restrict__ nw2, const float* __restrict__ nb2,
    const float* __restrict__ nw3, const float* __restrict__ nb3,
    const float* __restrict__ ng,  const float* __restrict__ nbt,
    float* __restrict__ outN)
{
    __shared__ float nin[NROWS][NODE_IN];
    __shared__ float h[NROWS][CS];
    __shared__ float sred[NROWS][8], s2red[NROWS][8];
    const int r0 = blockIdx.x * NROWS;
    const int tid = threadIdx.x;

    for (int x = tid; x < NROWS * NODE_IN; x += 256)
        nin[x / NODE_IN][x % NODE_IN] = g_NIN[r0 * NODE_IN + x];
    __syncthreads();

    float a[NROWS];
    #pragma unroll
    for (int r = 0; r < NROWS; r++) a[r] = nb1[tid];
    #pragma unroll 4
    for (int k = 0; k < NODE_IN; k++) {
        float w = nw1[k * CS + tid];
        #pragma unroll
        for (int r = 0; r < NROWS; r++) a[r] = fmaf(nin[r][k], w, a[r]);
    }
    #pragma unroll
    for (int r = 0; r < NROWS; r++) h[r][tid] = fmaxf(a[r], 0.f);
    __syncthreads();

    #pragma unroll
    for (int r = 0; r < NROWS; r++) a[r] = nb2[tid];
    #pragma unroll 4
    for (int k = 0; k < CS; k++) {
        float w = nw2[k * CS + tid];
        #pragma unroll
        for (int r = 0; r < NROWS; r++) a[r] = fmaf(h[r][k], w, a[r]);
    }
    __syncthreads();
    #pragma unroll
    for (int r = 0; r < NROWS; r++) h[r][tid] = fmaxf(a[r], 0.f);
    __syncthreads();

    #pragma unroll
    for (int r = 0; r < NROWS; r++) a[r] = nb3[tid];
    #pragma unroll 4
    for (int k = 0; k < CS; k++) {
        float w = nw3[k * CS + tid];
        #pragma unroll
        for (int r = 0; r < NROWS; r++) a[r] = fmaf(h[r][k], w, a[r]);
    }

    // LayerNorm over 256 cols, per row
    #pragma unroll
    for (int r = 0; r < NROWS; r++) {
        float s = a[r], s2 = a[r] * a[r];
        #pragma unroll
        for (int o = 16; o > 0; o >>= 1) {
            s  += __shfl_xor_sync(0xffffffffu, s,  o);
            s2 += __shfl_xor_sync(0xffffffffu, s2, o);
        }
        if ((tid & 31) == 0) { sred[r][tid >> 5] = s; s2red[r][tid >> 5] = s2; }
    }
    __syncthreads();
    float gv = ng[tid], bv = nbt[tid];
    #pragma unroll
    for (int r = 0; r < NROWS; r++) {
        float S = 0.f, S2 = 0.f;
        #pragma unroll
        for (int w = 0; w < 8; w++) { S += sred[r][w]; S2 += s2red[r][w]; }
        float mu = S * (1.0f / CS);
        float var = S2 * (1.0f / CS) - mu * mu;
        float rs = rsqrtf(var + 1e-5f);
        outN[(r0 + r) * CS + tid] = (a[r] - mu) * rs * gv + bv;
    }
}

// ---------------- kernel 4: edge MLP (dominant) ----------------
// 512 threads, each owns an 8(m) x 4(n) output tile. FFMA2 pairs along m.
__global__ __launch_bounds__(512, 1) void edge_kernel(
    const int* __restrict__ seq_idx, const float* __restrict__ sc_trans,
    const float* __restrict__ ew1, const float* __restrict__ eb1,
    const float* __restrict__ ew2, const float* __restrict__ eb2,
    const float* __restrict__ ew3, const float* __restrict__ eb3,
    const float* __restrict__ eg,  const float* __restrict__ ebt,
    float* __restrict__ outE)
{
    extern __shared__ float sm[];
    float* W2s  = sm;                       // 128*128
    float* W3s  = W2s + CZ * CZ;            // 128*128
    float* Hs   = W3s + CZ * CZ;            // 128*HP  (k-major: Hs[k][m])
    float* base = Hs + CZ * HP;             // 128
    int*  relS  = (int*)(base + CZ);        // 128
    int*  binS  = relS + CZ;                // 128

    const int jt = blockIdx.x, i = blockIdx.y, b = blockIdx.z;
    const int j0 = jt * 128;
    const int tid = threadIdx.x;
    const int row_i = b * NRES + i;

    // weights -> smem
    {
        const float4* w2v = (const float4*)ew2;
        const float4* w3v = (const float4*)ew3;
        float4* W2v = (float4*)W2s;
        float4* W3v = (float4*)W3s;
        for (int x = tid; x < (CZ * CZ) / 4; x += 512) { W2v[x] = w2v[x]; W3v[x] = w3v[x]; }
    }
    if (tid < CZ) base[tid] = g_NA[row_i * CZ + tid] + eb1[tid];
    if (tid >= 128 && tid < 256) {
        const int m = tid - 128;
        const int j = j0 + m;
        const int row_j = b * NRES + j;
        int r = seq_idx[row_i] - seq_idx[row_j] + 383;
        relS[m] = min(max(r, 0), 766);
        float dx = sc_trans[row_i * 3 + 0] - sc_trans[row_j * 3 + 0];
        float dy = sc_trans[row_i * 3 + 1] - sc_trans[row_j * 3 + 1];
        float dz = sc_trans[row_i * 3 + 2] - sc_trans[row_j * 3 + 2];
        float d = sqrtf(dx * dx + dy * dy + dz * dz);
        int bin = -1;
        const double step = (20.0 - 1e-05) / 21.0;
        #pragma unroll
        for (int k = 0; k < 22; k++) {
            float lo = (float)(1e-05 + k * step);
            float hi = (k < 21) ? (float)(1e-05 + (k + 1) * step) : 1e8f;
            if (d > lo && d < hi) bin = k;
        }
        binS[m] = bin;
    }
    __syncthreads();

    // layer 1 via factorization: h1[m][k] = relu(base[k] + B[j][k] + REL[rel][k] + dgram_row[k])
    {
        const int k = tid & 127;
        const int mb = (tid >> 7) * 32;
        const float bk = base[k];
        const float* nbp = g_NB + ((size_t)b * NRES + j0) * CZ + k;
        #pragma unroll 4
        for (int mm = 0; mm < 32; mm++) {
            const int m = mb + mm;
            float v = bk + nbp[(size_t)m * CZ] + g_REL[relS[m] * CZ + k];
            int bi = binS[m];
            if (bi >= 0) v += ew1[(178 + bi) * CZ + k];
            Hs[k * HP + m] = fmaxf(v, 0.f);
        }
    }
    __syncthreads();

    const int tx = tid & 31, ty = tid >> 5;      // warp = one ty (8 m rows)
    const int n0 = tx * 4, m0 = ty * 8;

    u64 acc[4][4];     // acc[rp][c]: rows (m0+2rp, m0+2rp+1), col n0+c

    // ---- GEMM 1: h2 = relu(h1 @ W2 + b2) ----
    #pragma unroll
    for (int rp = 0; rp < 4; rp++)
        #pragma unroll
        for (int c = 0; c < 4; c++) acc[rp][c] = 0ULL;

    #pragma unroll 4
    for (int k = 0; k < CZ; k++) {
        ulonglong2 aA = *(const ulonglong2*)&Hs[k * HP + m0];      // (m0,m0+1),(m0+2,m0+3)
        ulonglong2 aB = *(const ulonglong2*)&Hs[k * HP + m0 + 4];  // (m0+4,5),(6,7)
        float4 bv = *(const float4*)&W2s[k * CZ + n0];
        u64 b0 = pack2(bv.x), b1 = pack2(bv.y), b2 = pack2(bv.z), b3 = pack2(bv.w);
        ffma2(acc[0][0], aA.x, b0); ffma2(acc[0][1], aA.x, b1);
        ffma2(acc[0][2], aA.x, b2); ffma2(acc[0][3], aA.x, b3);
        ffma2(acc[1][0], aA.y, b0); ffma2(acc[1][1], aA.y, b1);
        ffma2(acc[1][2], aA.y, b2); ffma2(acc[1][3], aA.y, b3);
        ffma2(acc[2][0], aB.x, b0); ffma2(acc[2][1], aB.x, b1);
        ffma2(acc[2][2], aB.x, b2); ffma2(acc[2][3], aB.x, b3);
        ffma2(acc[3][0], aB.y, b0); ffma2(acc[3][1], aB.y, b1);
        ffma2(acc[3][2], aB.y, b2); ffma2(acc[3][3], aB.y, b3);
    }

    float h2v[8][4];
    #pragma unroll
    for (int c = 0; c < 4; c++) {
        float bc = eb2[n0 + c];
        #pragma unroll
        for (int rp = 0; rp < 4; rp++) {
            float2 v = unpack2(acc[rp][c]);
            h2v[2 * rp][c]     = fmaxf(v.x + bc, 0.f);
            h2v[2 * rp + 1][c] = fmaxf(v.y + bc, 0.f);
        }
    }
    __syncthreads();
    // store h2 transposed back into Hs (k-major for GEMM2)
    #pragma unroll
    for (int c = 0; c < 4; c++) {
        *(float4*)&Hs[(n0 + c) * HP + m0] =
            make_float4(h2v[0][c], h2v[1][c], h2v[2][c], h2v[3][c]);
        *(float4*)&Hs[(n0 + c) * HP + m0 + 4] =
            make_float4(h2v[4][c], h2v[5][c], h2v[6][c], h2v[7][c]);
    }
    __syncthreads();

    // ---- GEMM 2: h3 = h2 @ W3 + b3 ----
    #pragma unroll
    for (int rp = 0; rp < 4; rp++)
        #pragma unroll
        for (int c = 0; c < 4; c++) acc[rp][c] = 0ULL;

    #pragma unroll 4
    for (int k = 0; k < CZ; k++) {
        ulonglong2 aA = *(const ulonglong2*)&Hs[k * HP + m0];
        ulonglong2 aB = *(const ulonglong2*)&Hs[k * HP + m0 + 4];
        float4 bv = *(const float4*)&W3s[k * CZ + n0];
        u64 b0 = pack2(bv.x), b1 = pack2(bv.y), b2 = pack2(bv.z), b3 = pack2(bv.w);
        ffma2(acc[0][0], aA.x, b0); ffma2(acc[0][1], aA.x, b1);
        ffma2(acc[0][2], aA.x, b2); ffma2(acc[0][3], aA.x, b3);
        ffma2(acc[1][0], aA.y, b0); ffma2(acc[1][1], aA.y, b1);
        ffma2(acc[1][2], aA.y, b2); ffma2(acc[1][3], aA.y, b3);
        ffma2(acc[2][0], aB.x, b0); ffma2(acc[2][1], aB.x, b1);
        ffma2(acc[2][2], aB.x, b2); ffma2(acc[2][3], aB.x, b3);
        ffma2(acc[3][0], aB.y, b0); ffma2(acc[3][1], aB.y, b1);
        ffma2(acc[3][2], aB.y, b2); ffma2(acc[3][3], aB.y, b3);
    }

    float h3v[8][4];
    #pragma unroll
    for (int c = 0; c < 4; c++) {
        float bc = eb3[n0 + c];
        #pragma unroll
        for (int rp = 0; rp < 4; rp++) {
            float2 v = unpack2(acc[rp][c]);
            h3v[2 * rp][c]     = v.x + bc;
            h3v[2 * rp + 1][c] = v.y + bc;
        }
    }

    // ---- LayerNorm over n (128) per row m, full-warp reduction ----
    float egv[4], ebv[4];
    #pragma unroll
    for (int c = 0; c < 4; c++) { egv[c] = eg[n0 + c]; ebv[c] = ebt[n0 + c]; }

    #pragma unroll
    for (int r = 0; r < 8; r++) {
        float s = 0.f, s2 = 0.f;
        #pragma unroll
        for (int c = 0; c < 4; c++) { float v = h3v[r][c]; s += v; s2 += v * v; }
        #pragma unroll
        for (int o = 16; o > 0; o >>= 1) {
            s  += __shfl_xor_sync(0xffffffffu, s,  o);
            s2 += __shfl_xor_sync(0xffffffffu, s2, o);
        }
        float mu = s * (1.0f / CZ);
        float var = s2 * (1.0f / CZ) - mu * mu;
        float rs = rsqrtf(var + 1e-5f);
        const int m = j0 + m0 + r;
        float* op = outE + ((((size_t)b * NRES + i) * NRES) + m) * CZ + n0;
        *(float4*)op = make_float4(
            (h3v[r][0] - mu) * rs * egv[0] + ebv[0],
            (h3v[r][1] - mu) * rs * egv[1] + ebv[1],
            (h3v[r][2] - mu) * rs * egv[2] + ebv[2],
            (h3v[r][3] - mu) * rs * egv[3] + ebv[3]);
    }
}

// ---------------- launch ----------------
extern "C" void kernel_launch(void* const* d_in, const int* in_sizes, int n_in,
                              void* d_out, int out_size)
{
    const float* atom10     = (const float*)d_in[0];
    const int*   seq_idx    = (const int*)  d_in[1];
    const float* t          = (const float*)d_in[2];
    const float* fixed_mask = (const float*)d_in[3];
    /* d_in[4] node_mask unused */
    const float* sc_trans   = (const float*)d_in[5];
    const float* sc_rots    = (const float*)d_in[6];
    const float* sc_atom14  = (const float*)d_in[7];
    const float* nw1 = (const float*)d_in[8];
    const float* nb1 = (const float*)d_in[9];
    const float* nw2 = (const float*)d_in[10];
    const float* nb2 = (const float*)d_in[11];
    const float* nw3 = (const float*)d_in[12];
    const float* nb3 = (const float*)d_in[13];
    const float* ng  = (const float*)d_in[14];
    const float* nbt = (const float*)d_in[15];
    const float* ew1 = (const float*)d_in[16];
    const float* eb1 = (const float*)d_in[17];
    const float* ew2 = (const float*)d_in[18];
    const float* eb2 = (const float*)d_in[19];
    const float* ew3 = (const float*)d_in[20];
    const float* eb3 = (const float*)d_in[21];
    const float* eg  = (const float*)d_in[22];
    const float* ebt = (const float*)d_in[23];

    float* outN = (float*)d_out;
    float* outE = outN + (size_t)BB * NRES * CS;   // node first, then edge

    const int smem_edge = (CZ * CZ * 2 + CZ * HP + CZ) * 4 + 2 * CZ * 4;
    cudaFuncSetAttribute(edge_kernel, cudaFuncAttributeMaxDynamicSharedMemorySize, smem_edge);

    prep_node_kernel<<<BB * NRES, 128>>>(atom10, seq_idx, t, fixed_mask,
                                         sc_trans, sc_rots, sc_atom14, ew1);
    prep_rel_kernel<<<767, 128>>>(ew1);
    node_mlp_kernel<<<BB * NRES / NROWS, 256>>>(nw1, nb1, nw2, nb2, nw3, nb3, ng, nbt, outN);
    edge_kernel<<<dim3(NRES / 128, NRES, BB), 512, smem_edge>>>(
        seq_idx, sc_trans, ew1, eb1, ew2, eb2, ew3, eb3, eg, ebt, outE);
}